// round 14
// baseline (speedup 1.0000x reference)
#include <cuda_runtime.h>
#include <math.h>

#define VOCAB  32000
#define Q4     8000     // float4 per row
#define KNN    32
#define NT     256
#define NPAIR  592      // reader/writer pairs (grid = 2*NPAIR = 8 CTAs/SM exactly)
#define WINDOW 384      // reader may run at most this many rows ahead of writers
#define LOG2E  1.4426950408889634f

__device__ int   g_flags[1024];
__device__ float g_lscale[1024];
__device__ int   g_wdone;

__device__ __forceinline__ float warp_max(float v) {
    #pragma unroll
    for (int o = 16; o > 0; o >>= 1) v = fmaxf(v, __shfl_xor_sync(0xFFFFFFFFu, v, o));
    return v;
}
__device__ __forceinline__ float warp_sum(float v) {
    #pragma unroll
    for (int o = 16; o > 0; o >>= 1) v += __shfl_xor_sync(0xFFFFFFFFu, v, o);
    return v;
}
__device__ __forceinline__ float4 ldlu4(const float4* p) {
    float4 r;
    asm volatile("ld.global.lu.v4.f32 {%0,%1,%2,%3}, [%4];"
                 : "=f"(r.x), "=f"(r.y), "=f"(r.z), "=f"(r.w) : "l"(p));
    return r;
}
__device__ __forceinline__ void stcs4(float4* p, float4 v) {
    asm volatile("st.global.cs.v4.f32 [%0], {%1,%2,%3,%4};"
                 :: "l"(p), "f"(v.x), "f"(v.y), "f"(v.z), "f"(v.w) : "memory");
}
__device__ __forceinline__ void st_release(int* p, int v) {
    asm volatile("st.global.release.gpu.b32 [%0], %1;" :: "l"(p), "r"(v) : "memory");
}
__device__ __forceinline__ int ld_acquire(const int* p) {
    int v;
    asm volatile("ld.global.acquire.gpu.b32 %0, [%1];" : "=r"(v) : "l"(p) : "memory");
    return v;
}

__global__ void init_kernel() {
    const int i = threadIdx.x;
    g_flags[i] = 0;
    if (i == 0) g_wdone = 0;
}

__global__ __launch_bounds__(NT, 8)
void knn_model_kernel(const float* __restrict__ logits,
                      const int*   __restrict__ optor_vals,
                      const float* __restrict__ optor_dists,
                      const int*   __restrict__ const_vals,
                      const float* __restrict__ const_dists,
                      const int*   __restrict__ prev_words,
                      const float* __restrict__ optor_lamda,
                      const float* __restrict__ const_lamda,
                      const float* __restrict__ optor_temp,
                      const float* __restrict__ const_temp,
                      float*       __restrict__ out,
                      int          rows)
{
    __shared__ float red[8];

    const int role = blockIdx.x & 1;          // 0 = reader, 1 = writer
    const int id   = blockIdx.x >> 1;         // 0..NPAIR-1
    const int tid  = threadIdx.x;
    const int wid  = tid >> 5;
    const int lane = tid & 31;

    if (role == 0) {
        // ======================= READER =======================
        const float ol = optor_lamda[0];
        const float cl = const_lamda[0];

        for (int r = id; r < rows; r += NPAIR) {
            // throttle: keep L2 footprint bounded (logits lines must survive
            // until the matching writer reloads them)
            if (tid == 0) {
                while (*((volatile int*)&g_wdone) < r - WINDOW) __nanosleep(256);
            }
            __syncthreads();

            const float4* __restrict__ l4 = (const float4*)(logits + (size_t)r * VOCAB);
            float s = 0.0f;
            #pragma unroll 4
            for (int i = tid; i < Q4; i += NT) {
                float4 x = l4[i];
                s += exp2f(x.x * LOG2E) + exp2f(x.y * LOG2E)
                   + exp2f(x.z * LOG2E) + exp2f(x.w * LOG2E);
            }
            s = warp_sum(s);
            if (lane == 0) red[wid] = s;
            __syncthreads();
            if (tid < 32) {
                float v = (lane < 8) ? red[lane] : 0.0f;
                v = warp_sum(v);
                if (lane == 0) {
                    const int p = prev_words[r];
                    const bool om = (p <= 88) | ((p >= 91) & (p <= 291));
                    const bool cm = (p == 89) | (p == 90) | (p >= 292);
                    const float base = (om ? (1.0f - ol) : 0.0f)
                                     + (cm ? (1.0f - cl) : 0.0f);
                    g_lscale[r] = log2f(base / v);   // base > 0 (masks exhaustive)
                    st_release(&g_flags[r], 1);      // publish
                }
            }
            __syncthreads();
        }
    } else {
        // ======================= WRITER =======================
        for (int r = id; r < rows; r += NPAIR) {
            if (tid == 0) {
                while (ld_acquire(&g_flags[r]) == 0) __nanosleep(128);
            }
            __syncthreads();                  // lscale[r] now safely readable block-wide
            const float lscale = g_lscale[r];

            const float4* __restrict__ l4 = (const float4*)(logits + (size_t)r * VOCAB);
            float4* __restrict__ o4 = (float4*)(out + (size_t)r * VOCAB);
            float*  __restrict__ orow = out + (size_t)r * VOCAB;

            #pragma unroll 4
            for (int i = tid; i < Q4; i += NT) {
                float4 x = ldlu4(&l4[i]);     // L2 hit (reader streamed it), last-use
                float4 y;
                y.x = exp2f(fmaf(x.x, LOG2E, lscale));
                y.y = exp2f(fmaf(x.y, LOG2E, lscale));
                y.z = exp2f(fmaf(x.z, LOG2E, lscale));
                y.w = exp2f(fmaf(x.w, LOG2E, lscale));
                stcs4(&o4[i], y);
            }
            __syncthreads();                  // base stores before scatter atomics

            if (wid == 0) {
                const int p = prev_words[r];
                const bool om = (p <= 88) | ((p >= 91) & (p <= 291));
                const float t = optor_temp[0];
                const float d = optor_dists[(size_t)r * KNN + lane];
                const float x = -d / t;
                const float mm = warp_max(x);
                const float e  = __expf(x - mm);
                const float ss = warp_sum(e);
                if (om) atomicAdd(&orow[optor_vals[(size_t)r * KNN + lane]],
                                  optor_lamda[0] * e / ss);
            } else if (wid == 1) {
                const int p = prev_words[r];
                const bool cm = (p == 89) | (p == 90) | (p >= 292);
                const float t = const_temp[0];
                const float d = const_dists[(size_t)r * KNN + lane];
                const float x = -d / t;
                const float mm = warp_max(x);
                const float e  = __expf(x - mm);
                const float ss = warp_sum(e);
                if (cm) atomicAdd(&orow[const_vals[(size_t)r * KNN + lane]],
                                  const_lamda[0] * e / ss);
            } else if (wid == 2 && lane == 0) {
                atomicAdd(&g_wdone, 1);       // advance reader window
            }
            __syncthreads();
        }
    }
}

extern "C" void kernel_launch(void* const* d_in, const int* in_sizes, int n_in,
                              void* d_out, int out_size)
{
    const float* logits      = (const float*)d_in[0];
    const int*   optor_vals  = (const int*)  d_in[1];
    const float* optor_dists = (const float*)d_in[2];
    const int*   const_vals  = (const int*)  d_in[3];
    const float* const_dists = (const float*)d_in[4];
    const int*   prev_words  = (const int*)  d_in[5];
    const float* optor_lamda = (const float*)d_in[6];
    const float* const_lamda = (const float*)d_in[7];
    const float* optor_temp  = (const float*)d_in[8];
    const float* const_temp  = (const float*)d_in[9];
    float* out = (float*)d_out;

    const int rows = in_sizes[5];                 // B*S = 1024

    init_kernel<<<1, 1024>>>();
    knn_model_kernel<<<NPAIR * 2, NT>>>(
        logits, optor_vals, optor_dists, const_vals, const_dists,
        prev_words, optor_lamda, const_lamda, optor_temp, const_temp, out, rows);
}

// round 15
// speedup vs baseline: 1.4275x; 1.4275x over previous
#include <cuda_runtime.h>
#include <math.h>

#define VOCAB 32000
#define Q4    8000     // float4 per row
#define KNN   32
#define NT    512
#define LOG2E 1.4426950408889634f

__device__ __forceinline__ float warp_max(float v) {
    #pragma unroll
    for (int o = 16; o > 0; o >>= 1) v = fmaxf(v, __shfl_xor_sync(0xFFFFFFFFu, v, o));
    return v;
}
__device__ __forceinline__ float warp_sum(float v) {
    #pragma unroll
    for (int o = 16; o > 0; o >>= 1) v += __shfl_xor_sync(0xFFFFFFFFu, v, o);
    return v;
}

__device__ __forceinline__ float4 ldlu4(const float4* p) {
    float4 r;
    asm volatile("ld.global.lu.v4.f32 {%0,%1,%2,%3}, [%4];"
                 : "=f"(r.x), "=f"(r.y), "=f"(r.z), "=f"(r.w) : "l"(p));
    return r;
}
__device__ __forceinline__ void stcs4(float4* p, float4 v) {
    asm volatile("st.global.cs.v4.f32 [%0], {%1,%2,%3,%4};"
                 :: "l"(p), "f"(v.x), "f"(v.y), "f"(v.z), "f"(v.w) : "memory");
}

__global__ __launch_bounds__(NT, 4)
void knn_model_kernel(const float* __restrict__ logits,
                      const int*   __restrict__ optor_vals,
                      const float* __restrict__ optor_dists,
                      const int*   __restrict__ const_vals,
                      const float* __restrict__ const_dists,
                      const int*   __restrict__ prev_words,
                      const float* __restrict__ optor_lamda,
                      const float* __restrict__ const_lamda,
                      const float* __restrict__ optor_temp,
                      const float* __restrict__ const_temp,
                      float*       __restrict__ out)
{
    __shared__ float red[16];
    __shared__ float lscale_sh;

    const int r    = blockIdx.x;              // one row per CTA
    const int tid  = threadIdx.x;
    const int wid  = tid >> 5;
    const int lane = tid & 31;

    const float4* __restrict__ l4 = (const float4*)(logits + (size_t)r * VOCAB);
    float4* __restrict__ o4 = (float4*)(out + (size_t)r * VOCAB);
    float*  __restrict__ orow = out + (size_t)r * VOCAB;

    // ---- Early scatter-input prefetch (latency overlaps pass A) ----
    float sc_d = 0.0f; int sc_v = 0; float sc_t = 1.0f, sc_l = 0.0f;
    const int p = prev_words[r];
    if (wid == 0) {
        sc_d = optor_dists[(size_t)r * KNN + lane];
        sc_v = optor_vals [(size_t)r * KNN + lane];
        sc_t = optor_temp[0];
        sc_l = optor_lamda[0];
    } else if (wid == 1) {
        sc_d = const_dists[(size_t)r * KNN + lane];
        sc_v = const_vals [(size_t)r * KNN + lane];
        sc_t = const_temp[0];
        sc_l = const_lamda[0];
    }

    // ---- Pass A: read logits (DRAM -> L2), exp2(x*log2e), block sum ----
    float s = 0.0f;
    #pragma unroll 4
    for (int i = tid; i < Q4; i += NT) {
        float4 x = l4[i];
        s += exp2f(x.x * LOG2E) + exp2f(x.y * LOG2E)
           + exp2f(x.z * LOG2E) + exp2f(x.w * LOG2E);
    }

    // ---- Prefetch first pass-C chunk (L2 reload latency hides under barrier) ----
    float4 pf = ldlu4(&l4[tid]);

    s = warp_sum(s);
    if (lane == 0) red[wid] = s;
    __syncthreads();
    if (tid < 32) {
        float v = (lane < 16) ? red[lane] : 0.0f;
        v = warp_sum(v);
        if (lane == 0) {
            const int pw = p;  // prev_words[r] already loaded
            const bool om = (pw <= 88) | ((pw >= 91) & (pw <= 291));
            const bool cm = (pw == 89) | (pw == 90) | (pw >= 292);
            const float base = (om ? (1.0f - optor_lamda[0]) : 0.0f)
                             + (cm ? (1.0f - const_lamda[0]) : 0.0f);
            lscale_sh = log2f(base / v);      // base > 0 always (masks exhaustive)
        }
    }
    __syncthreads();
    const float lscale = lscale_sh;

    // ---- Pass C: prefetched first chunk, then stream the rest ----
    {
        float4 y;
        y.x = exp2f(fmaf(pf.x, LOG2E, lscale));
        y.y = exp2f(fmaf(pf.y, LOG2E, lscale));
        y.z = exp2f(fmaf(pf.z, LOG2E, lscale));
        y.w = exp2f(fmaf(pf.w, LOG2E, lscale));
        stcs4(&o4[tid], y);
    }
    #pragma unroll 4
    for (int i = tid + NT; i < Q4; i += NT) {
        float4 x = ldlu4(&l4[i]);
        float4 y;
        y.x = exp2f(fmaf(x.x, LOG2E, lscale));
        y.y = exp2f(fmaf(x.y, LOG2E, lscale));
        y.z = exp2f(fmaf(x.z, LOG2E, lscale));
        y.w = exp2f(fmaf(x.w, LOG2E, lscale));
        stcs4(&o4[i], y);
    }
    __syncthreads();   // all base stores issued before scatter atomics

    // ---- Scatter: warp 0 = optor, warp 1 = const (inputs prefetched) ----
    if (wid < 2) {
        bool m;
        if (wid == 0) m = (p <= 88) | ((p >= 91) & (p <= 291));
        else          m = (p == 89) | (p == 90) | (p >= 292);
        const float x = -sc_d / sc_t;
        const float mm = warp_max(x);
        const float e  = __expf(x - mm);
        const float ss = warp_sum(e);
        if (m) atomicAdd(&orow[sc_v], sc_l * e / ss);
    }
}

extern "C" void kernel_launch(void* const* d_in, const int* in_sizes, int n_in,
                              void* d_out, int out_size)
{
    const float* logits      = (const float*)d_in[0];
    const int*   optor_vals  = (const int*)  d_in[1];
    const float* optor_dists = (const float*)d_in[2];
    const int*   const_vals  = (const int*)  d_in[3];
    const float* const_dists = (const float*)d_in[4];
    const int*   prev_words  = (const int*)  d_in[5];
    const float* optor_lamda = (const float*)d_in[6];
    const float* const_lamda = (const float*)d_in[7];
    const float* optor_temp  = (const float*)d_in[8];
    const float* const_temp  = (const float*)d_in[9];
    float* out = (float*)d_out;

    const int rows = in_sizes[5];                 // B*S = 1024

    knn_model_kernel<<<rows, NT>>>(
        logits, optor_vals, optor_dists, const_vals, const_dists,
        prev_words, optor_lamda, const_lamda, optor_temp, const_temp, out);
}